// round 14
// baseline (speedup 1.0000x reference)
#include <cuda_runtime.h>
#include <cuda_bf16.h>
#include <cstdint>

#define NUTT 64
#define SEQL 512
#define DIM  256
#define G3   768

// ---------------- scratch (__device__ globals; no allocation) --------------
__device__ float g_gx[(size_t)NUTT * SEQL * G3];     // ~100.7 MB
__device__ float g_hh[(size_t)NUTT * SEQL * DIM];    // ~33.6 MB
__device__ float g_utt[NUTT * DIM];

// ---------------- packed f32x2 helpers (Blackwell FFMA2) -------------------
__device__ __forceinline__ unsigned long long pk2(float x, float y) {
    unsigned long long d;
    asm("mov.b64 %0, {%1, %2};" : "=l"(d) : "f"(x), "f"(y));
    return d;
}
__device__ __forceinline__ float2 upk2(unsigned long long v) {
    float2 r;
    asm("mov.b64 {%0, %1}, %2;" : "=f"(r.x), "=f"(r.y) : "l"(v));
    return r;
}
__device__ __forceinline__ unsigned long long fma2(unsigned long long a,
                                                   unsigned long long b,
                                                   unsigned long long c) {
    unsigned long long d;
    asm("fma.rn.f32x2 %0, %1, %2, %3;" : "=l"(d) : "l"(a), "l"(b), "l"(c));
    return d;
}
__device__ __forceinline__ unsigned smem_u32(const void* p) {
    unsigned a;
    asm("{ .reg .u64 t; cvta.to.shared.u64 t, %1; cvt.u32.u64 %0, t; }"
        : "=r"(a) : "l"(p));
    return a;
}
__device__ __forceinline__ unsigned long long lds64(unsigned addr) {
    unsigned long long v;
    asm volatile("ld.shared.b64 %0, [%1];" : "=l"(v) : "r"(addr));
    return v;
}
__device__ __forceinline__ void st_cluster_f32(unsigned saddr, unsigned rank, float v) {
    asm volatile(
        "{\n\t"
        ".reg .u32 ra;\n\t"
        "mapa.shared::cluster.u32 ra, %0, %1;\n\t"
        "st.shared::cluster.f32 [ra], %2;\n\t"
        "}" :: "r"(saddr), "r"(rank), "f"(v) : "memory");
}
__device__ __forceinline__ unsigned my_cluster_rank() {
    unsigned r;
    asm("mov.u32 %0, %%cluster_ctarank;" : "=r"(r));
    return r;
}
__device__ __forceinline__ float sigf(float x) {
    return 1.0f / (1.0f + __expf(-x));
}
#define CLUSTER_SYNC_() do { \
    asm volatile("barrier.cluster.arrive.aligned;" ::: "memory"); \
    asm volatile("barrier.cluster.wait.aligned;"   ::: "memory"); } while (0)

// ---------------------------------------------------------------------------
// Kernel 1: g_gx[m][n] = embed[tokens[m]] . Wih[n] + bih[n]
// m in [0,32768), n in [0,768). Tiles 64x64, K chunks of 64 stored k-paired:
// Xs2[k2][mn] = float2{X[2k2][mn], X[2k2+1][mn]}.
// ---------------------------------------------------------------------------
__global__ void __launch_bounds__(256)
gx_gemm_kernel(const int* __restrict__ tokens, const float* __restrict__ embed,
               const float* __restrict__ Wih, const float* __restrict__ bih) {
    __shared__ __align__(16) float2 As2[32 * 64];
    __shared__ __align__(16) float2 Bs2[32 * 64];

    const int tid = threadIdx.x;
    const int bm = blockIdx.x, bn = blockIdx.y;

    // loader role: row within tile + column quarter
    const int lr = tid >> 2;          // 0..63
    const int lq = tid & 3;           // 0..3 (16 k's each)
    const int tok = tokens[bm * 64 + lr];
    const float* Arow = embed + (size_t)tok * DIM;
    const float* Brow = Wih + (size_t)(bn * 64 + lr) * DIM;

    // compute role: 4x4 microtile
    const int tn = tid & 15;          // n quad
    const int tm = tid >> 4;          // m quad
    const unsigned aBase = smem_u32(As2) + (unsigned)(tm * 4) * 8u;
    const unsigned bBase = smem_u32(Bs2) + (unsigned)(tn * 4) * 8u;

    unsigned long long acc[4][4];
#pragma unroll
    for (int i = 0; i < 4; i++)
#pragma unroll
        for (int j = 0; j < 4; j++) acc[i][j] = 0ull;

#pragma unroll 1
    for (int kc = 0; kc < 4; kc++) {
        __syncthreads();
#pragma unroll
        for (int s = 0; s < 4; s++) {
            const int kb = lq * 16 + s * 4;
            float4 a = *(const float4*)(Arow + kc * 64 + kb);
            float4 b = *(const float4*)(Brow + kc * 64 + kb);
            As2[(kb >> 1) * 64 + lr]       = make_float2(a.x, a.y);
            As2[((kb >> 1) + 1) * 64 + lr] = make_float2(a.z, a.w);
            Bs2[(kb >> 1) * 64 + lr]       = make_float2(b.x, b.y);
            Bs2[((kb >> 1) + 1) * 64 + lr] = make_float2(b.z, b.w);
        }
        __syncthreads();

#pragma unroll
        for (int k2 = 0; k2 < 32; k2++) {
            const unsigned off = (unsigned)(k2 * 64) * 8u;
            unsigned long long a2[4], b2[4];
#pragma unroll
            for (int i = 0; i < 4; i++) a2[i] = lds64(aBase + off + i * 8u);
#pragma unroll
            for (int j = 0; j < 4; j++) b2[j] = lds64(bBase + off + j * 8u);
#pragma unroll
            for (int i = 0; i < 4; i++)
#pragma unroll
                for (int j = 0; j < 4; j++)
                    acc[i][j] = fma2(a2[i], b2[j], acc[i][j]);
        }
    }

    // epilogue
    const int n0 = bn * 64 + tn * 4;
    float4 bias = *(const float4*)(bih + n0);
#pragma unroll
    for (int i = 0; i < 4; i++) {
        const size_t m = (size_t)bm * 64 + tm * 4 + i;
        float2 s0 = upk2(acc[i][0]);
        float2 s1 = upk2(acc[i][1]);
        float2 s2 = upk2(acc[i][2]);
        float2 s3 = upk2(acc[i][3]);
        float4 o;
        o.x = s0.x + s0.y + bias.x;
        o.y = s1.x + s1.y + bias.y;
        o.z = s2.x + s2.y + bias.z;
        o.w = s3.x + s3.y + bias.w;
        *(float4*)(g_gx + m * G3 + n0) = o;
    }
}

// ---------------------------------------------------------------------------
// Kernel 2: word GRU, 512 sequential steps. Cluster of 4 CTAs; each CTA owns
// hidden slice [64*rank, 64*rank+64): gate rows {u, 256+u, 512+u}.
// Weights register-resident: 384 threads, thread = (row 0..191, khalf 0..1),
// each holds 128 W floats as 64 packed f32x2. Cluster handles 2 batches.
// ---------------------------------------------------------------------------
__global__ void __launch_bounds__(384, 1) __cluster_dims__(4, 1, 1)
gru_word_kernel(const float* __restrict__ Whh, const float* __restrict__ bhh) {
    __shared__ __align__(16) float hbuf[2][2][DIM];   // parity, batch, unit
    __shared__ float2 red[192];
    __shared__ float2 ghb[192];
    __shared__ float2 gxb[192];

    const int tid = threadIdx.x;
    const unsigned rank = my_cluster_rank();
    const int cid = blockIdx.x >> 2;
    const int b0 = cid * 2, b1 = b0 + 1;

    const int row = tid % 192;            // local gate row
    const int kh  = tid / 192;            // k half 0/1
    const int useg = row >> 6;            // 0:r 1:z 2:n
    const int uu   = row & 63;
    const int grow = useg * 256 + (int)rank * 64 + uu;

    // load weights into registers (packed over adjacent k)
    unsigned long long w[64];
    {
        const float2* wr = (const float2*)(Whh + (size_t)grow * DIM + kh * 128);
#pragma unroll
        for (int i = 0; i < 64; i++) {
            float2 v = wr[i];
            w[i] = pk2(v.x, v.y);
        }
    }
    const float bias = bhh[grow];

    // zero initial h
    for (int i = tid; i < 2 * DIM; i += 384) ((float*)hbuf[0])[i] = 0.0f;
    __syncthreads();
    CLUSTER_SYNC_();

    const float* gx0 = g_gx + (size_t)b0 * SEQL * G3;
    const float* gx1 = g_gx + (size_t)b1 * SEQL * G3;
    float* hh0 = g_hh + (size_t)b0 * SEQL * DIM;
    float* hh1 = g_hh + (size_t)b1 * SEQL * DIM;

    const unsigned hbase = smem_u32(hbuf);

    for (int t = 0; t < SEQL; t++) {
        const int par = t & 1;

        // prefetch gx for this step (consumed after reduction)
        float xg0 = 0.0f, xg1 = 0.0f;
        if (kh == 0) {
            xg0 = __ldg(gx0 + (size_t)t * G3 + grow);
            xg1 = __ldg(gx1 + (size_t)t * G3 + grow);
        }

        // gemv: acc over this thread's 128-wide k slice, both batches
        unsigned long long acc0 = 0ull, acc1 = 0ull;
        {
            const unsigned hb0 = hbase + (unsigned)(par * 2 * DIM) * 4u
                                        + (unsigned)(kh * 128) * 4u;
            const unsigned hb1 = hb0 + DIM * 4u;
#pragma unroll
            for (int i = 0; i < 64; i++) {
                unsigned long long h20 = lds64(hb0 + i * 8u);
                unsigned long long h21 = lds64(hb1 + i * 8u);
                acc0 = fma2(w[i], h20, acc0);
                acc1 = fma2(w[i], h21, acc1);
            }
        }
        float2 p0 = upk2(acc0), p1 = upk2(acc1);
        float s0 = p0.x + p0.y;
        float s1 = p1.x + p1.y;

        if (kh == 1) red[row] = make_float2(s0, s1);
        __syncthreads();
        if (kh == 0) {
            float2 o = red[row];
            ghb[row] = make_float2(s0 + o.x + bias, s1 + o.y + bias);
            gxb[row] = make_float2(xg0, xg1);
        }
        __syncthreads();

        // gate combine: threads 0..63, one hidden unit each, both batches
        if (tid < 64) {
            const int u = tid;
            float2 gr = ghb[u],      xr = gxb[u];
            float2 gz = ghb[64 + u], xz = gxb[64 + u];
            float2 gn = ghb[128 + u], xn = gxb[128 + u];

            float r0 = sigf(xr.x + gr.x);
            float z0 = sigf(xz.x + gz.x);
            float n0 = tanhf(xn.x + r0 * gn.x);
            float hp0 = hbuf[par][0][rank * 64 + u];
            float h0 = (1.0f - z0) * n0 + z0 * hp0;

            float r1 = sigf(xr.y + gr.y);
            float z1 = sigf(xz.y + gz.y);
            float n1 = tanhf(xn.y + r1 * gn.y);
            float hp1 = hbuf[par][1][rank * 64 + u];
            float h1 = (1.0f - z1) * n1 + z1 * hp1;

            // broadcast into next-parity buffer of ALL 4 CTAs
            const unsigned a0 = hbase + (unsigned)((par ^ 1) * 2 * DIM
                                 + rank * 64 + u) * 4u;
            const unsigned a1 = a0 + DIM * 4u;
#pragma unroll
            for (unsigned rk = 0; rk < 4; rk++) {
                st_cluster_f32(a0, rk, h0);
                st_cluster_f32(a1, rk, h1);
            }
            // history for the attention-pool pass
            hh0[(size_t)t * DIM + rank * 64 + u] = h0;
            hh1[(size_t)t * DIM + rank * 64 + u] = h1;
        }
        CLUSTER_SYNC_();
    }
}

// ---------------------------------------------------------------------------
// Kernel 3: attention pool over T=512 per batch -> g_utt
// ---------------------------------------------------------------------------
__global__ void __launch_bounds__(256)
pool_kernel(const float* __restrict__ uaw, const float* __restrict__ uab) {
    __shared__ float sw[DIM];
    __shared__ float lg[SEQL];
    __shared__ float rbuf[256];
    __shared__ float sM, sS;

    const int b = blockIdx.x;
    const int tid = threadIdx.x;
    const int wid = tid >> 5, lane = tid & 31;
    const float* H = g_hh + (size_t)b * SEQL * DIM;

    sw[tid] = uaw[tid];
    __syncthreads();

    // logits: one warp per timestep (strided)
    for (int t = wid; t < SEQL; t += 8) {
        const float* h = H + (size_t)t * DIM;
        float s = 0.0f;
#pragma unroll
        for (int j = 0; j < 8; j++)
            s += h[lane + 32 * j] * sw[lane + 32 * j];
#pragma unroll
        for (int o = 16; o > 0; o >>= 1)
            s += __shfl_xor_sync(0xffffffffu, s, o);
        if (lane == 0) lg[t] = s + uab[0];
    }
    __syncthreads();

    // softmax max
    float m = fmaxf(lg[tid], lg[tid + 256]);
    rbuf[tid] = m;
    __syncthreads();
    for (int s = 128; s > 0; s >>= 1) {
        if (tid < s) rbuf[tid] = fmaxf(rbuf[tid], rbuf[tid + s]);
        __syncthreads();
    }
    if (tid == 0) sM = rbuf[0];
    __syncthreads();

    float e0 = __expf(lg[tid] - sM);
    float e1 = __expf(lg[tid + 256] - sM);
    __syncthreads();
    lg[tid] = e0;
    lg[tid + 256] = e1;
    rbuf[tid] = e0 + e1;
    __syncthreads();
    for (int s = 128; s > 0; s >>= 1) {
        if (tid < s) rbuf[tid] += rbuf[tid + s];
        __syncthreads();
    }
    if (tid == 0) sS = rbuf[0];
    __syncthreads();

    // weighted sum over t (coalesced over d = tid)
    float acc = 0.0f;
    const float inv = 1.0f / sS;
#pragma unroll 8
    for (int t = 0; t < SEQL; t++)
        acc += lg[t] * H[(size_t)t * DIM + tid];
    g_utt[b * DIM + tid] = acc * inv;
}

// ---------------------------------------------------------------------------
// Kernel 4: sentence GRU (T=1, h0=0 -> gh = bhh; sg_Whh dead) + trivial
// dialog pool (T=1 softmax = identity). out = (1-z)*n.
// ---------------------------------------------------------------------------
__global__ void __launch_bounds__(256)
sent_kernel(const float* __restrict__ Wih, const float* __restrict__ bih,
            const float* __restrict__ bhh, float* __restrict__ out) {
    __shared__ float x[DIM];
    const int b = blockIdx.x;
    const int u = threadIdx.x;

    x[u] = g_utt[b * DIM + u];
    __syncthreads();

    float a[3];
#pragma unroll
    for (int g = 0; g < 3; g++) {
        const float4* W = (const float4*)(Wih + (size_t)(g * DIM + u) * DIM);
        float s = bih[g * DIM + u];
#pragma unroll 8
        for (int i = 0; i < 64; i++) {
            float4 w4 = W[i];
            s += w4.x * x[4 * i] + w4.y * x[4 * i + 1]
               + w4.z * x[4 * i + 2] + w4.w * x[4 * i + 3];
        }
        a[g] = s;
    }
    float r = sigf(a[0] + bhh[u]);
    float z = sigf(a[1] + bhh[DIM + u]);
    float n = tanhf(a[2] + r * bhh[2 * DIM + u]);
    out[b * DIM + u] = (1.0f - z) * n;
}

// ---------------------------------------------------------------------------
extern "C" void kernel_launch(void* const* d_in, const int* in_sizes, int n_in,
                              void* d_out, int out_size) {
    const int*   tokens = (const int*)d_in[0];
    const float* embed  = (const float*)d_in[1];
    const float* wgWih  = (const float*)d_in[2];
    const float* wgWhh  = (const float*)d_in[3];
    const float* wgbih  = (const float*)d_in[4];
    const float* wgbhh  = (const float*)d_in[5];
    const float* uaw    = (const float*)d_in[6];
    const float* uab    = (const float*)d_in[7];
    const float* sgWih  = (const float*)d_in[8];
    // d_in[9] = sg_Whh (dead: h0 = 0), d_in[12..13] = da_w/da_b (dead: T=1)
    const float* sgbih  = (const float*)d_in[10];
    const float* sgbhh  = (const float*)d_in[11];
    float* out = (float*)d_out;

    dim3 ggrid(512, 12);
    gx_gemm_kernel<<<ggrid, 256>>>(tokens, embed, wgWih, wgbih);
    gru_word_kernel<<<128, 384>>>(wgWhh, wgbhh);
    pool_kernel<<<NUTT, 256>>>(uaw, uab);
    sent_kernel<<<NUTT, 256>>>(sgWih, sgbih, sgbhh, out);
}